// round 14
// baseline (speedup 1.0000x reference)
#include <cuda_runtime.h>
#include <cuda_fp16.h>
#include <mma.h>
#include <cstdint>
#include <math.h>

using namespace nvcuda;

#define T_TOK 2048
#define DM    2048
#define FM    8192
#define EM    4
#define KM    2

// ---------------- scratch ----------------------------------------------------
__device__ int    g_count[EM];
__device__ int    g_bucket[EM * T_TOK];
__device__ float  g_gate[EM * T_TOK];
__device__ int    g_slot[T_TOK * KM];
__device__ __half g_xh[T_TOK * DM];                  // x half, [t][d]
__device__ __half g_Wgh[(size_t)EM * DM * FM];       // Wg half, natural [e][d][f]
__device__ __half g_Wuh[(size_t)EM * DM * FM];       // Wu half, natural [e][d][f]
__device__ __half g_Wdh[(size_t)EM * FM * DM];       // Wd half, natural [e][f][d]
__device__ __half g_Hh[(size_t)EM * T_TOK * FM];     // hidden half, [slot][f]
__device__ float  g_Y[(size_t)EM * T_TOK * DM];      // per-slot output fp32

// ---------------- helpers ----------------------------------------------------
__device__ __forceinline__ float silu_f(float x) { return x / (1.0f + expf(-x)); }

__device__ __forceinline__ uint32_t smem_u32(const void* p) {
    uint32_t a;
    asm("{ .reg .u64 t; cvta.to.shared.u64 t, %1; cvt.u32.u64 %0, t; }" : "=r"(a) : "l"(p));
    return a;
}

__device__ __forceinline__ void cpa16(uint32_t dst, const void* src, uint32_t sz) {
    asm volatile("cp.async.cg.shared.global [%0], [%1], 16, %2;\n"
                 :: "r"(dst), "l"(src), "r"(sz));
}
#define CP_COMMIT() asm volatile("cp.async.commit_group;\n" ::: "memory")
#define CP_WAIT3()  asm volatile("cp.async.wait_group 3;\n" ::: "memory")

// ---------------- prep kernels ------------------------------------------------
__global__ void init_counts_kernel() { if (threadIdx.x < EM) g_count[threadIdx.x] = 0; }

__global__ void cvt_x_kernel(const float* __restrict__ x) {
    const int i = blockIdx.x * 256 + threadIdx.x;      // float4 index
    float4 v = ((const float4*)x)[i];
    __half2 h0 = __floats2half2_rn(v.x, v.y);
    __half2 h1 = __floats2half2_rn(v.z, v.w);
    uint2 o;
    o.x = *(uint32_t*)&h0; o.y = *(uint32_t*)&h1;
    ((uint2*)g_xh)[i] = o;
}

// streaming fp32 -> fp16, all three weights in one launch (blockIdx.y selects)
__global__ void cvt_w_kernel(const float* __restrict__ Wg,
                             const float* __restrict__ Wu,
                             const float* __restrict__ Wd) {
    const int which = blockIdx.y;
    const float* src = (which == 0) ? Wg : (which == 1) ? Wu : Wd;
    __half* dst = (which == 0) ? g_Wgh : (which == 1) ? g_Wuh : g_Wdh;
    const size_t i = (size_t)blockIdx.x * 256 + threadIdx.x;   // float4 index
    float4 v = ((const float4*)src)[i];
    __half2 h0 = __floats2half2_rn(v.x, v.y);
    __half2 h1 = __floats2half2_rn(v.z, v.w);
    uint2 o;
    o.x = *(uint32_t*)&h0; o.y = *(uint32_t*)&h1;
    ((uint2*)dst)[i] = o;
}

__global__ void router_kernel(const float* __restrict__ x, const float* __restrict__ Wr) {
    const int t = blockIdx.x, tid = threadIdx.x;
    const float* xr = x + (size_t)t * DM;
    float acc[EM] = {0.f, 0.f, 0.f, 0.f};
    for (int d = tid; d < DM; d += 128) {
        const float xv = xr[d];
#pragma unroll
        for (int e = 0; e < EM; e++) acc[e] += xv * Wr[d * EM + e];
    }
    __shared__ float sred[EM][128];
#pragma unroll
    for (int e = 0; e < EM; e++) sred[e][tid] = acc[e];
    __syncthreads();
    for (int s = 64; s > 0; s >>= 1) {
        if (tid < s) {
#pragma unroll
            for (int e = 0; e < EM; e++) sred[e][tid] += sred[e][tid + s];
        }
        __syncthreads();
    }
    if (tid == 0) {
        float l[EM];
#pragma unroll
        for (int e = 0; e < EM; e++) l[e] = sred[e][0];
        float mx = l[0];
#pragma unroll
        for (int e = 1; e < EM; e++) mx = fmaxf(mx, l[e]);
        float p[EM], sum = 0.f;
#pragma unroll
        for (int e = 0; e < EM; e++) { p[e] = expf(l[e] - mx); sum += p[e]; }
        const float inv = 1.0f / sum;
#pragma unroll
        for (int e = 0; e < EM; e++) p[e] *= inv;
        int e0 = 0;
#pragma unroll
        for (int e = 1; e < EM; e++) if (p[e] > p[e0]) e0 = e;
        int e1 = -1;
#pragma unroll
        for (int e = 0; e < EM; e++) {
            if (e == e0) continue;
            if (e1 < 0 || p[e] > p[e1]) e1 = e;
        }
        int s0 = atomicAdd(&g_count[e0], 1);
        g_bucket[e0 * T_TOK + s0] = t; g_gate[e0 * T_TOK + s0] = p[e0];
        g_slot[t * KM + 0] = e0 * T_TOK + s0;
        int s1 = atomicAdd(&g_count[e1], 1);
        g_bucket[e1 * T_TOK + s1] = t; g_gate[e1 * T_TOK + s1] = p[e1];
        g_slot[t * KM + 1] = e1 * T_TOK + s1;
    }
}

// =============== GEMM1: H = silu(x Wg) * (x Wu), wmma =========================
// Block 128M x 64F dual. 8 warps: wm=warp&3 (4x32M), wn=warp>>2 (2x32F).
// 5-stage cp.async pipeline, prefetch distance 4, wait_group(3).
#define G1_AP 40
#define G1_BPn 72
#define G1_AB (128 * G1_AP * 2)            // 10240
#define G1_BB (32 * G1_BPn * 2)            // 4608
#define G1_STAGE (G1_AB + 2 * G1_BB)       // 19456
#define G1_NS 5
#define G1_PIPE  (G1_NS * G1_STAGE)        // 97280
#define G1_SMEM  (G1_PIPE + 512)

__global__ __launch_bounds__(256, 2)
void gemm1_kernel() {
    extern __shared__ char sm[];
    const int e   = blockIdx.z;
    const int cnt = g_count[e];
    const int m0  = blockIdx.x * 128;
    if (m0 >= cnt) return;
    const int f0  = blockIdx.y * 64;

    const int tid = threadIdx.x, warp = tid >> 5;
    const int wm = warp & 3, wn = warp >> 2;
    const uint32_t sb = smem_u32(sm);
    int* rows = (int*)(sm + G1_PIPE);

    if (tid < 128) {
        const int m = m0 + tid;
        rows[tid] = (m < cnt) ? g_bucket[e * T_TOK + m] : -1;
    }
    __syncthreads();

    const __half* Wge = g_Wgh + (size_t)e * DM * FM + f0;   // [d][f] natural
    const __half* Wue = g_Wuh + (size_t)e * DM * FM + f0;

    auto load_tile = [&](int s, int kt) {
        const int k0 = kt * 32;
        const uint32_t ab = sb + s * G1_STAGE;
#pragma unroll
        for (int p = 0; p < 2; p++) {                  // A: 128 rows x 4 chunks
            const int idx = tid + p * 256;
            const int rr = idx >> 2, c = idx & 3;
            const int tok = rows[rr];
            const __half* src = (tok >= 0) ? (g_xh + (size_t)tok * DM + k0 + c * 8) : g_xh;
            cpa16(ab + rr * (G1_AP * 2) + c * 16, src, (tok >= 0) ? 16u : 0u);
        }
        {   // Bg: 32 k-rows x 8 chunks (128B/row)
            const int kr = tid >> 3, c = tid & 7;
            cpa16(ab + G1_AB + kr * (G1_BPn * 2) + c * 16,
                  Wge + (size_t)(k0 + kr) * FM + c * 8, 16);
        }
        {   // Bu
            const int kr = tid >> 3, c = tid & 7;
            cpa16(ab + G1_AB + G1_BB + kr * (G1_BPn * 2) + c * 16,
                  Wue + (size_t)(k0 + kr) * FM + c * 8, 16);
        }
    };

    wmma::fragment<wmma::accumulator, 16, 16, 16, float> cG[2][2], cU[2][2];
#pragma unroll
    for (int mi = 0; mi < 2; mi++)
#pragma unroll
        for (int ni = 0; ni < 2; ni++) {
            wmma::fill_fragment(cG[mi][ni], 0.0f);
            wmma::fill_fragment(cU[mi][ni], 0.0f);
        }

    const int KT = DM / 32;   // 64
    load_tile(0, 0); CP_COMMIT();
    load_tile(1, 1); CP_COMMIT();
    load_tile(2, 2); CP_COMMIT();
    load_tile(3, 3); CP_COMMIT();

    int ls = 4, cs = 0;   // next load stage, current compute stage
    for (int kt = 0; kt < KT; kt++) {
        CP_WAIT3();
        __syncthreads();
        // stage ls == (kt-1) mod 5: all warps finished reading it (barrier above)
        if (kt + 4 < KT) {
            load_tile(ls, kt + 4);
            if (++ls == G1_NS) ls = 0;
        }

        const __half* As = (const __half*)(sm + cs * G1_STAGE);
        if (++cs == G1_NS) cs = 0;
        const __half* Bg = As + 128 * G1_AP;
        const __half* Bu = Bg + 32 * G1_BPn;

#pragma unroll
        for (int ks = 0; ks < 2; ks++) {
            wmma::fragment<wmma::matrix_b, 16, 16, 16, __half, wmma::row_major> fbG[2], fbU[2];
#pragma unroll
            for (int ni = 0; ni < 2; ni++) {
                wmma::load_matrix_sync(fbG[ni], Bg + ks * 16 * G1_BPn + wn * 32 + ni * 16, G1_BPn);
                wmma::load_matrix_sync(fbU[ni], Bu + ks * 16 * G1_BPn + wn * 32 + ni * 16, G1_BPn);
            }
#pragma unroll
            for (int mi = 0; mi < 2; mi++) {
                wmma::fragment<wmma::matrix_a, 16, 16, 16, __half, wmma::row_major> fa;
                wmma::load_matrix_sync(fa, As + (wm * 32 + mi * 16) * G1_AP + ks * 16, G1_AP);
#pragma unroll
                for (int ni = 0; ni < 2; ni++) {
                    wmma::mma_sync(cG[mi][ni], fa, fbG[ni], cG[mi][ni]);
                    wmma::mma_sync(cU[mi][ni], fa, fbU[ni], cU[mi][ni]);
                }
            }
        }
        CP_COMMIT();
    }

    // epilogue: stage accs to smem (reuse pipeline memory), fuse silu, write half H
    __syncthreads();
    float* sg = (float*)sm;                 // 128x64 floats = 32KB
    float* su = sg + 128 * 64;              // next 32KB
#pragma unroll
    for (int mi = 0; mi < 2; mi++)
#pragma unroll
        for (int ni = 0; ni < 2; ni++) {
            const int r = wm * 32 + mi * 16, c = wn * 32 + ni * 16;
            wmma::store_matrix_sync(sg + r * 64 + c, cG[mi][ni], 64, wmma::mem_row_major);
            wmma::store_matrix_sync(su + r * 64 + c, cU[mi][ni], 64, wmma::mem_row_major);
        }
    __syncthreads();
    for (int i = tid; i < 128 * 64; i += 256) {
        const int r = i >> 6, c = i & 63;
        const float g = sg[i], u = su[i];
        g_Hh[((size_t)(e * T_TOK) + m0 + r) * FM + f0 + c] = __float2half_rn(silu_f(g) * u);
    }
}

// =============== GEMM2: Y = H Wd, wmma ========================================
// Block 128M x 128N. 8 warps: wm=warp&1 (2x64M), wn=warp>>1 (4x32N).
// 5-stage cp.async pipeline, prefetch distance 4, wait_group(3).
#define G2_AP 40
#define G2_BPn 136
#define G2_AB (128 * G2_AP * 2)             // 10240
#define G2_BB (32 * G2_BPn * 2)             // 8704
#define G2_STAGE (G2_AB + G2_BB)            // 18944
#define G2_NS 5
#define G2_SMEM  (G2_NS * G2_STAGE)         // 94720

__global__ __launch_bounds__(256, 2)
void gemm2_kernel() {
    extern __shared__ char sm[];
    const int e   = blockIdx.z;
    const int cnt = g_count[e];
    const int m0  = blockIdx.x * 128;
    if (m0 >= cnt) return;
    const int d0  = blockIdx.y * 128;

    const int tid = threadIdx.x, warp = tid >> 5;
    const int wm = warp & 1, wn = warp >> 1;
    const uint32_t sb = smem_u32(sm);

    const __half* Hb  = g_Hh + (size_t)(e * T_TOK + m0) * FM;
    const __half* Wde = g_Wdh + (size_t)e * FM * DM + d0;    // [f][d] natural

    auto load_tile = [&](int s, int kt) {
        const int k0 = kt * 32;
        const uint32_t ab = sb + s * G2_STAGE;
#pragma unroll
        for (int p = 0; p < 2; p++) {                  // A: 512 chunks
            const int idx = tid + p * 256;
            const int rr = idx >> 2, c = idx & 3;
            cpa16(ab + rr * (G2_AP * 2) + c * 16, Hb + (size_t)rr * FM + k0 + c * 8, 16);
        }
#pragma unroll
        for (int p = 0; p < 2; p++) {                  // B: 32 rows x 16 chunks
            const int idx = tid + p * 256;
            const int kr = idx >> 4, c = idx & 15;
            cpa16(ab + G2_AB + kr * (G2_BPn * 2) + c * 16,
                  Wde + (size_t)(k0 + kr) * DM + c * 8, 16);
        }
    };

    wmma::fragment<wmma::accumulator, 16, 16, 16, float> cY[4][2];
#pragma unroll
    for (int mi = 0; mi < 4; mi++)
#pragma unroll
        for (int ni = 0; ni < 2; ni++)
            wmma::fill_fragment(cY[mi][ni], 0.0f);

    const int KT = FM / 32;   // 256
    load_tile(0, 0); CP_COMMIT();
    load_tile(1, 1); CP_COMMIT();
    load_tile(2, 2); CP_COMMIT();
    load_tile(3, 3); CP_COMMIT();

    int ls = 4, cs = 0;
    for (int kt = 0; kt < KT; kt++) {
        CP_WAIT3();
        __syncthreads();
        if (kt + 4 < KT) {
            load_tile(ls, kt + 4);
            if (++ls == G2_NS) ls = 0;
        }

        const __half* As = (const __half*)(sm + cs * G2_STAGE);
        if (++cs == G2_NS) cs = 0;
        const __half* Bs = As + 128 * G2_AP;

#pragma unroll
        for (int ks = 0; ks < 2; ks++) {
            wmma::fragment<wmma::matrix_b, 16, 16, 16, __half, wmma::row_major> fb[2];
#pragma unroll
            for (int ni = 0; ni < 2; ni++)
                wmma::load_matrix_sync(fb[ni], Bs + ks * 16 * G2_BPn + wn * 32 + ni * 16, G2_BPn);
#pragma unroll
            for (int mi = 0; mi < 4; mi++) {
                wmma::fragment<wmma::matrix_a, 16, 16, 16, __half, wmma::row_major> fa;
                wmma::load_matrix_sync(fa, As + (wm * 64 + mi * 16) * G2_AP + ks * 16, G2_AP);
#pragma unroll
                for (int ni = 0; ni < 2; ni++)
                    wmma::mma_sync(cY[mi][ni], fa, fb[ni], cY[mi][ni]);
            }
        }
        CP_COMMIT();
    }

    // direct gmem store (fp32, ldm = DM)
#pragma unroll
    for (int mi = 0; mi < 4; mi++)
#pragma unroll
        for (int ni = 0; ni < 2; ni++) {
            float* dst = g_Y + ((size_t)(e * T_TOK) + m0 + wm * 64 + mi * 16) * DM
                             + d0 + wn * 32 + ni * 16;
            wmma::store_matrix_sync(dst, cY[mi][ni], DM, wmma::mem_row_major);
        }
}

__global__ void combine_kernel(float* __restrict__ out) {
    const int i = blockIdx.x * blockDim.x + threadIdx.x;
    const int t = i / (DM / 4), c = i % (DM / 4);
    const int s0 = g_slot[t * KM + 0], s1 = g_slot[t * KM + 1];
    const float w0 = g_gate[s0], w1 = g_gate[s1];
    const float4 y0 = *((const float4*)g_Y + (size_t)s0 * (DM / 4) + c);
    const float4 y1 = *((const float4*)g_Y + (size_t)s1 * (DM / 4) + c);
    float4 o;
    o.x = w0 * y0.x + w1 * y1.x; o.y = w0 * y0.y + w1 * y1.y;
    o.z = w0 * y0.z + w1 * y1.z; o.w = w0 * y0.w + w1 * y1.w;
    *((float4*)out + i) = o;
}

// ---------------- launch ------------------------------------------------------
extern "C" void kernel_launch(void* const* d_in, const int* in_sizes, int n_in,
                              void* d_out, int out_size) {
    const float* x  = (const float*)d_in[0];
    const float* Wr = (const float*)d_in[1];
    const float* Wg = (const float*)d_in[2];
    const float* Wu = (const float*)d_in[3];
    const float* Wd = (const float*)d_in[4];
    float* out = (float*)d_out;

    cudaFuncSetAttribute(gemm1_kernel, cudaFuncAttributeMaxDynamicSharedMemorySize, G1_SMEM);
    cudaFuncSetAttribute(gemm2_kernel, cudaFuncAttributeMaxDynamicSharedMemorySize, G2_SMEM);

    const int WQ = (EM * DM * FM) / 4 / 256;     // float4 blocks per weight
    init_counts_kernel<<<1, 32>>>();
    cvt_x_kernel<<<T_TOK * DM / 4 / 256, 256>>>(x);
    cvt_w_kernel<<<dim3(WQ, 3), 256>>>(Wg, Wu, Wd);
    router_kernel<<<T_TOK, 128>>>(x, Wr);
    gemm1_kernel<<<dim3(T_TOK / 128, FM / 64, EM), 256, G1_SMEM>>>();
    gemm2_kernel<<<dim3(T_TOK / 128, DM / 128, EM), 256, G2_SMEM>>>();
    combine_kernel<<<(T_TOK * DM / 4) / 256, 256>>>(out);
}

// round 15
// speedup vs baseline: 1.0154x; 1.0154x over previous
#include <cuda_runtime.h>
#include <cuda_fp16.h>
#include <mma.h>
#include <cstdint>
#include <math.h>

using namespace nvcuda;

#define T_TOK 2048
#define DM    2048
#define FM    8192
#define EM    4
#define KM    2

// ---------------- scratch ----------------------------------------------------
__device__ int    g_count[EM];
__device__ int    g_bucket[EM * T_TOK];
__device__ float  g_gate[EM * T_TOK];
__device__ int    g_slot[T_TOK * KM];
__device__ __half g_xh[T_TOK * DM];                  // x half, [t][d]
__device__ __half g_Wgh[(size_t)EM * DM * FM];       // Wg half, natural [e][d][f]
__device__ __half g_Wuh[(size_t)EM * DM * FM];       // Wu half, natural [e][d][f]
__device__ __half g_Wdh[(size_t)EM * FM * DM];       // Wd half, natural [e][f][d]
__device__ __half g_Hh[(size_t)EM * T_TOK * FM];     // hidden half, [slot][f]
__device__ float  g_Y[(size_t)EM * T_TOK * DM];      // per-slot output fp32

// ---------------- helpers ----------------------------------------------------
__device__ __forceinline__ float silu_f(float x) { return x / (1.0f + expf(-x)); }

__device__ __forceinline__ uint32_t smem_u32(const void* p) {
    uint32_t a;
    asm("{ .reg .u64 t; cvta.to.shared.u64 t, %1; cvt.u32.u64 %0, t; }" : "=r"(a) : "l"(p));
    return a;
}

__device__ __forceinline__ void cpa16(uint32_t dst, const void* src, uint32_t sz) {
    asm volatile("cp.async.cg.shared.global [%0], [%1], 16, %2;\n"
                 :: "r"(dst), "l"(src), "r"(sz));
}
#define CP_COMMIT() asm volatile("cp.async.commit_group;\n" ::: "memory")
#define CP_WAIT1()  asm volatile("cp.async.wait_group 1;\n" ::: "memory")

// ---------------- prep kernels ------------------------------------------------
__global__ void init_counts_kernel() { if (threadIdx.x < EM) g_count[threadIdx.x] = 0; }

__global__ void cvt_x_kernel(const float* __restrict__ x) {
    const int i = blockIdx.x * 256 + threadIdx.x;      // float4 index
    float4 v = ((const float4*)x)[i];
    __half2 h0 = __floats2half2_rn(v.x, v.y);
    __half2 h1 = __floats2half2_rn(v.z, v.w);
    uint2 o;
    o.x = *(uint32_t*)&h0; o.y = *(uint32_t*)&h1;
    ((uint2*)g_xh)[i] = o;
}

// streaming fp32 -> fp16, all three weights in one launch (blockIdx.y selects)
__global__ void cvt_w_kernel(const float* __restrict__ Wg,
                             const float* __restrict__ Wu,
                             const float* __restrict__ Wd) {
    const int which = blockIdx.y;
    const float* src = (which == 0) ? Wg : (which == 1) ? Wu : Wd;
    __half* dst = (which == 0) ? g_Wgh : (which == 1) ? g_Wuh : g_Wdh;
    const size_t i = (size_t)blockIdx.x * 256 + threadIdx.x;   // float4 index
    float4 v = ((const float4*)src)[i];
    __half2 h0 = __floats2half2_rn(v.x, v.y);
    __half2 h1 = __floats2half2_rn(v.z, v.w);
    uint2 o;
    o.x = *(uint32_t*)&h0; o.y = *(uint32_t*)&h1;
    ((uint2*)dst)[i] = o;
}

__global__ void router_kernel(const float* __restrict__ x, const float* __restrict__ Wr) {
    const int t = blockIdx.x, tid = threadIdx.x;
    const float* xr = x + (size_t)t * DM;
    float acc[EM] = {0.f, 0.f, 0.f, 0.f};
    for (int d = tid; d < DM; d += 128) {
        const float xv = xr[d];
#pragma unroll
        for (int e = 0; e < EM; e++) acc[e] += xv * Wr[d * EM + e];
    }
    __shared__ float sred[EM][128];
#pragma unroll
    for (int e = 0; e < EM; e++) sred[e][tid] = acc[e];
    __syncthreads();
    for (int s = 64; s > 0; s >>= 1) {
        if (tid < s) {
#pragma unroll
            for (int e = 0; e < EM; e++) sred[e][tid] += sred[e][tid + s];
        }
        __syncthreads();
    }
    if (tid == 0) {
        float l[EM];
#pragma unroll
        for (int e = 0; e < EM; e++) l[e] = sred[e][0];
        float mx = l[0];
#pragma unroll
        for (int e = 1; e < EM; e++) mx = fmaxf(mx, l[e]);
        float p[EM], sum = 0.f;
#pragma unroll
        for (int e = 0; e < EM; e++) { p[e] = expf(l[e] - mx); sum += p[e]; }
        const float inv = 1.0f / sum;
#pragma unroll
        for (int e = 0; e < EM; e++) p[e] *= inv;
        int e0 = 0;
#pragma unroll
        for (int e = 1; e < EM; e++) if (p[e] > p[e0]) e0 = e;
        int e1 = -1;
#pragma unroll
        for (int e = 0; e < EM; e++) {
            if (e == e0) continue;
            if (e1 < 0 || p[e] > p[e1]) e1 = e;
        }
        int s0 = atomicAdd(&g_count[e0], 1);
        g_bucket[e0 * T_TOK + s0] = t; g_gate[e0 * T_TOK + s0] = p[e0];
        g_slot[t * KM + 0] = e0 * T_TOK + s0;
        int s1 = atomicAdd(&g_count[e1], 1);
        g_bucket[e1 * T_TOK + s1] = t; g_gate[e1 * T_TOK + s1] = p[e1];
        g_slot[t * KM + 1] = e1 * T_TOK + s1;
    }
}

// =============== GEMM1: H = silu(x Wg) * (x Wu), wmma, BK=64 ==================
// Block 128M x 64F dual. 8 warps: wm=warp&3 (4x32M), wn=warp>>2 (2x32F).
// 3-stage cp.async pipeline, prefetch distance 2, wait_group(1). 32 k-iters.
#define G1_AP 72                           // A pitch halves (64 k + 8 pad)
#define G1_BPn 72                          // B pitch halves (64 f + 8 pad)
#define G1_AB (128 * G1_AP * 2)            // 18432
#define G1_BB (64 * G1_BPn * 2)            // 9216
#define G1_STAGE (G1_AB + 2 * G1_BB)       // 36864
#define G1_NS 3
#define G1_PIPE  (G1_NS * G1_STAGE)        // 110592
#define G1_SMEM  (G1_PIPE + 512)

__global__ __launch_bounds__(256, 2)
void gemm1_kernel() {
    extern __shared__ char sm[];
    const int e   = blockIdx.z;
    const int cnt = g_count[e];
    const int m0  = blockIdx.x * 128;
    if (m0 >= cnt) return;
    const int f0  = blockIdx.y * 64;

    const int tid = threadIdx.x, warp = tid >> 5;
    const int wm = warp & 3, wn = warp >> 2;
    const uint32_t sb = smem_u32(sm);
    int* rows = (int*)(sm + G1_PIPE);

    if (tid < 128) {
        const int m = m0 + tid;
        rows[tid] = (m < cnt) ? g_bucket[e * T_TOK + m] : -1;
    }
    __syncthreads();

    const __half* Wge = g_Wgh + (size_t)e * DM * FM + f0;   // [d][f] natural
    const __half* Wue = g_Wuh + (size_t)e * DM * FM + f0;

    auto load_tile = [&](int s, int kt) {
        const int k0 = kt * 64;
        const uint32_t ab = sb + s * G1_STAGE;
#pragma unroll
        for (int p = 0; p < 4; p++) {                  // A: 128 rows x 8 chunks = 1024
            const int idx = tid + p * 256;
            const int rr = idx >> 3, c = idx & 7;
            const int tok = rows[rr];
            const __half* src = (tok >= 0) ? (g_xh + (size_t)tok * DM + k0 + c * 8) : g_xh;
            cpa16(ab + rr * (G1_AP * 2) + c * 16, src, (tok >= 0) ? 16u : 0u);
        }
#pragma unroll
        for (int p = 0; p < 2; p++) {                  // Bg: 64 k-rows x 8 chunks = 512
            const int idx = tid + p * 256;
            const int kr = idx >> 3, c = idx & 7;
            cpa16(ab + G1_AB + kr * (G1_BPn * 2) + c * 16,
                  Wge + (size_t)(k0 + kr) * FM + c * 8, 16);
        }
#pragma unroll
        for (int p = 0; p < 2; p++) {                  // Bu
            const int idx = tid + p * 256;
            const int kr = idx >> 3, c = idx & 7;
            cpa16(ab + G1_AB + G1_BB + kr * (G1_BPn * 2) + c * 16,
                  Wue + (size_t)(k0 + kr) * FM + c * 8, 16);
        }
    };

    wmma::fragment<wmma::accumulator, 16, 16, 16, float> cG[2][2], cU[2][2];
#pragma unroll
    for (int mi = 0; mi < 2; mi++)
#pragma unroll
        for (int ni = 0; ni < 2; ni++) {
            wmma::fill_fragment(cG[mi][ni], 0.0f);
            wmma::fill_fragment(cU[mi][ni], 0.0f);
        }

    const int KT = DM / 64;   // 32
    load_tile(0, 0); CP_COMMIT();
    load_tile(1, 1); CP_COMMIT();

    for (int kt = 0; kt < KT; kt++) {
        CP_WAIT1();
        __syncthreads();
        if (kt + 2 < KT) load_tile((kt + 2) % 3, kt + 2);

        const __half* As = (const __half*)(sm + (kt % 3) * G1_STAGE);
        const __half* Bg = As + 128 * G1_AP;
        const __half* Bu = Bg + 64 * G1_BPn;

#pragma unroll
        for (int ks = 0; ks < 4; ks++) {
            wmma::fragment<wmma::matrix_b, 16, 16, 16, __half, wmma::row_major> fbG[2], fbU[2];
#pragma unroll
            for (int ni = 0; ni < 2; ni++) {
                wmma::load_matrix_sync(fbG[ni], Bg + ks * 16 * G1_BPn + wn * 32 + ni * 16, G1_BPn);
                wmma::load_matrix_sync(fbU[ni], Bu + ks * 16 * G1_BPn + wn * 32 + ni * 16, G1_BPn);
            }
#pragma unroll
            for (int mi = 0; mi < 2; mi++) {
                wmma::fragment<wmma::matrix_a, 16, 16, 16, __half, wmma::row_major> fa;
                wmma::load_matrix_sync(fa, As + (wm * 32 + mi * 16) * G1_AP + ks * 16, G1_AP);
#pragma unroll
                for (int ni = 0; ni < 2; ni++) {
                    wmma::mma_sync(cG[mi][ni], fa, fbG[ni], cG[mi][ni]);
                    wmma::mma_sync(cU[mi][ni], fa, fbU[ni], cU[mi][ni]);
                }
            }
        }
        CP_COMMIT();
    }

    // epilogue: stage accs to smem (reuse pipeline memory), fuse silu, write half H
    __syncthreads();
    float* sg = (float*)sm;                 // 128x64 floats = 32KB
    float* su = sg + 128 * 64;              // next 32KB
#pragma unroll
    for (int mi = 0; mi < 2; mi++)
#pragma unroll
        for (int ni = 0; ni < 2; ni++) {
            const int r = wm * 32 + mi * 16, c = wn * 32 + ni * 16;
            wmma::store_matrix_sync(sg + r * 64 + c, cG[mi][ni], 64, wmma::mem_row_major);
            wmma::store_matrix_sync(su + r * 64 + c, cU[mi][ni], 64, wmma::mem_row_major);
        }
    __syncthreads();
    for (int i = tid; i < 128 * 64; i += 256) {
        const int r = i >> 6, c = i & 63;
        const float g = sg[i], u = su[i];
        g_Hh[((size_t)(e * T_TOK) + m0 + r) * FM + f0 + c] = __float2half_rn(silu_f(g) * u);
    }
}

// =============== GEMM2: Y = H Wd, wmma, BK=64 =================================
// Block 128M x 128N. 8 warps: wm=warp&1 (2x64M), wn=warp>>1 (4x32N).
// 3-stage cp.async pipeline, prefetch distance 2, wait_group(1). 128 k-iters.
#define G2_AP 72
#define G2_BPn 136
#define G2_AB (128 * G2_AP * 2)             // 18432
#define G2_BB (64 * G2_BPn * 2)             // 17408
#define G2_STAGE (G2_AB + G2_BB)            // 35840
#define G2_NS 3
#define G2_SMEM  (G2_NS * G2_STAGE)         // 107520

__global__ __launch_bounds__(256, 2)
void gemm2_kernel() {
    extern __shared__ char sm[];
    const int e   = blockIdx.z;
    const int cnt = g_count[e];
    const int m0  = blockIdx.x * 128;
    if (m0 >= cnt) return;
    const int d0  = blockIdx.y * 128;

    const int tid = threadIdx.x, warp = tid >> 5;
    const int wm = warp & 1, wn = warp >> 1;
    const uint32_t sb = smem_u32(sm);

    const __half* Hb  = g_Hh + (size_t)(e * T_TOK + m0) * FM;
    const __half* Wde = g_Wdh + (size_t)e * FM * DM + d0;    // [f][d] natural

    auto load_tile = [&](int s, int kt) {
        const int k0 = kt * 64;
        const uint32_t ab = sb + s * G2_STAGE;
#pragma unroll
        for (int p = 0; p < 4; p++) {                  // A: 128 rows x 8 chunks = 1024
            const int idx = tid + p * 256;
            const int rr = idx >> 3, c = idx & 7;
            cpa16(ab + rr * (G2_AP * 2) + c * 16, Hb + (size_t)rr * FM + k0 + c * 8, 16);
        }
#pragma unroll
        for (int p = 0; p < 4; p++) {                  // B: 64 k-rows x 16 chunks = 1024
            const int idx = tid + p * 256;
            const int kr = idx >> 4, c = idx & 15;
            cpa16(ab + G2_AB + kr * (G2_BPn * 2) + c * 16,
                  Wde + (size_t)(k0 + kr) * DM + c * 8, 16);
        }
    };

    wmma::fragment<wmma::accumulator, 16, 16, 16, float> cY[4][2];
#pragma unroll
    for (int mi = 0; mi < 4; mi++)
#pragma unroll
        for (int ni = 0; ni < 2; ni++)
            wmma::fill_fragment(cY[mi][ni], 0.0f);

    const int KT = FM / 64;   // 128
    load_tile(0, 0); CP_COMMIT();
    load_tile(1, 1); CP_COMMIT();

    for (int kt = 0; kt < KT; kt++) {
        CP_WAIT1();
        __syncthreads();
        if (kt + 2 < KT) load_tile((kt + 2) % 3, kt + 2);

        const __half* As = (const __half*)(sm + (kt % 3) * G2_STAGE);
        const __half* Bs = As + 128 * G2_AP;

#pragma unroll
        for (int ks = 0; ks < 4; ks++) {
            wmma::fragment<wmma::matrix_b, 16, 16, 16, __half, wmma::row_major> fb[2];
#pragma unroll
            for (int ni = 0; ni < 2; ni++)
                wmma::load_matrix_sync(fb[ni], Bs + ks * 16 * G2_BPn + wn * 32 + ni * 16, G2_BPn);
#pragma unroll
            for (int mi = 0; mi < 4; mi++) {
                wmma::fragment<wmma::matrix_a, 16, 16, 16, __half, wmma::row_major> fa;
                wmma::load_matrix_sync(fa, As + (wm * 64 + mi * 16) * G2_AP + ks * 16, G2_AP);
#pragma unroll
                for (int ni = 0; ni < 2; ni++)
                    wmma::mma_sync(cY[mi][ni], fa, fb[ni], cY[mi][ni]);
            }
        }
        CP_COMMIT();
    }

    // direct gmem store (fp32, ldm = DM)
#pragma unroll
    for (int mi = 0; mi < 4; mi++)
#pragma unroll
        for (int ni = 0; ni < 2; ni++) {
            float* dst = g_Y + ((size_t)(e * T_TOK) + m0 + wm * 64 + mi * 16) * DM
                             + d0 + wn * 32 + ni * 16;
            wmma::store_matrix_sync(dst, cY[mi][ni], DM, wmma::mem_row_major);
        }
}

__global__ void combine_kernel(float* __restrict__ out) {
    const int i = blockIdx.x * blockDim.x + threadIdx.x;
    const int t = i / (DM / 4), c = i % (DM / 4);
    const int s0 = g_slot[t * KM + 0], s1 = g_slot[t * KM + 1];
    const float w0 = g_gate[s0], w1 = g_gate[s1];
    const float4 y0 = *((const float4*)g_Y + (size_t)s0 * (DM / 4) + c);
    const float4 y1 = *((const float4*)g_Y + (size_t)s1 * (DM / 4) + c);
    float4 o;
    o.x = w0 * y0.x + w1 * y1.x; o.y = w0 * y0.y + w1 * y1.y;
    o.z = w0 * y0.z + w1 * y1.z; o.w = w0 * y0.w + w1 * y1.w;
    *((float4*)out + i) = o;
}

// ---------------- launch ------------------------------------------------------
extern "C" void kernel_launch(void* const* d_in, const int* in_sizes, int n_in,
                              void* d_out, int out_size) {
    const float* x  = (const float*)d_in[0];
    const float* Wr = (const float*)d_in[1];
    const float* Wg = (const float*)d_in[2];
    const float* Wu = (const float*)d_in[3];
    const float* Wd = (const float*)d_in[4];
    float* out = (float*)d_out;

    cudaFuncSetAttribute(gemm1_kernel, cudaFuncAttributeMaxDynamicSharedMemorySize, G1_SMEM);
    cudaFuncSetAttribute(gemm2_kernel, cudaFuncAttributeMaxDynamicSharedMemorySize, G2_SMEM);

    const int WQ = (EM * DM * FM) / 4 / 256;     // float4 blocks per weight
    init_counts_kernel<<<1, 32>>>();
    cvt_x_kernel<<<T_TOK * DM / 4 / 256, 256>>>(x);
    cvt_w_kernel<<<dim3(WQ, 3), 256>>>(Wg, Wu, Wd);
    router_kernel<<<T_TOK, 128>>>(x, Wr);
    gemm1_kernel<<<dim3(T_TOK / 128, FM / 64, EM), 256, G1_SMEM>>>();
    gemm2_kernel<<<dim3(T_TOK / 128, DM / 128, EM), 256, G2_SMEM>>>();
    combine_kernel<<<(T_TOK * DM / 4) / 256, 256>>>(out);
}

// round 16
// speedup vs baseline: 1.0352x; 1.0195x over previous
#include <cuda_runtime.h>
#include <cuda_fp16.h>
#include <mma.h>
#include <cstdint>
#include <math.h>

using namespace nvcuda;

#define T_TOK 2048
#define DM    2048
#define FM    8192
#define EM    4
#define KM    2

// ---------------- scratch ----------------------------------------------------
__device__ int    g_count[EM];
__device__ int    g_bucket[EM * T_TOK];
__device__ float  g_gate[EM * T_TOK];
__device__ int    g_slot[T_TOK * KM];
__device__ __half g_xh[T_TOK * DM];                  // x half, [t][d]
__device__ __half g_Wgh[(size_t)EM * DM * FM];       // Wg half, natural [e][d][f]
__device__ __half g_Wuh[(size_t)EM * DM * FM];       // Wu half, natural [e][d][f]
__device__ __half g_Wdh[(size_t)EM * FM * DM];       // Wd half, natural [e][f][d]
__device__ __half g_Hh[(size_t)EM * T_TOK * FM];     // hidden half, [slot][f]
__device__ float  g_Y[(size_t)EM * T_TOK * DM];      // per-slot output fp32

// ---------------- helpers ----------------------------------------------------
__device__ __forceinline__ float silu_f(float x) { return x / (1.0f + expf(-x)); }

__device__ __forceinline__ uint32_t smem_u32(const void* p) {
    uint32_t a;
    asm("{ .reg .u64 t; cvta.to.shared.u64 t, %1; cvt.u32.u64 %0, t; }" : "=r"(a) : "l"(p));
    return a;
}

__device__ __forceinline__ void cpa16(uint32_t dst, const void* src, uint32_t sz) {
    asm volatile("cp.async.cg.shared.global [%0], [%1], 16, %2;\n"
                 :: "r"(dst), "l"(src), "r"(sz));
}
#define CP_COMMIT() asm volatile("cp.async.commit_group;\n" ::: "memory")
#define CP_WAIT1()  asm volatile("cp.async.wait_group 1;\n" ::: "memory")

// ---------------- prep kernels ------------------------------------------------
__global__ void init_counts_kernel() { if (threadIdx.x < EM) g_count[threadIdx.x] = 0; }

__global__ void cvt_x_kernel(const float* __restrict__ x) {
    const int i = blockIdx.x * 256 + threadIdx.x;      // float4 index
    float4 v = ((const float4*)x)[i];
    __half2 h0 = __floats2half2_rn(v.x, v.y);
    __half2 h1 = __floats2half2_rn(v.z, v.w);
    uint2 o;
    o.x = *(uint32_t*)&h0; o.y = *(uint32_t*)&h1;
    ((uint2*)g_xh)[i] = o;
}

// streaming fp32 -> fp16 for Wg, Wu only (Wd converted inside gemm1's grid)
__global__ void cvt_w_kernel(const float* __restrict__ Wg,
                             const float* __restrict__ Wu) {
    const int which = blockIdx.y;
    const float* src = (which == 0) ? Wg : Wu;
    __half* dst = (which == 0) ? g_Wgh : g_Wuh;
    const size_t i = (size_t)blockIdx.x * 256 + threadIdx.x;   // float4 index
    float4 v = ((const float4*)src)[i];
    __half2 h0 = __floats2half2_rn(v.x, v.y);
    __half2 h1 = __floats2half2_rn(v.z, v.w);
    uint2 o;
    o.x = *(uint32_t*)&h0; o.y = *(uint32_t*)&h1;
    ((uint2*)dst)[i] = o;
}

__global__ void router_kernel(const float* __restrict__ x, const float* __restrict__ Wr) {
    const int t = blockIdx.x, tid = threadIdx.x;
    const float* xr = x + (size_t)t * DM;
    float acc[EM] = {0.f, 0.f, 0.f, 0.f};
    for (int d = tid; d < DM; d += 128) {
        const float xv = xr[d];
#pragma unroll
        for (int e = 0; e < EM; e++) acc[e] += xv * Wr[d * EM + e];
    }
    __shared__ float sred[EM][128];
#pragma unroll
    for (int e = 0; e < EM; e++) sred[e][tid] = acc[e];
    __syncthreads();
    for (int s = 64; s > 0; s >>= 1) {
        if (tid < s) {
#pragma unroll
            for (int e = 0; e < EM; e++) sred[e][tid] += sred[e][tid + s];
        }
        __syncthreads();
    }
    if (tid == 0) {
        float l[EM];
#pragma unroll
        for (int e = 0; e < EM; e++) l[e] = sred[e][0];
        float mx = l[0];
#pragma unroll
        for (int e = 1; e < EM; e++) mx = fmaxf(mx, l[e]);
        float p[EM], sum = 0.f;
#pragma unroll
        for (int e = 0; e < EM; e++) { p[e] = expf(l[e] - mx); sum += p[e]; }
        const float inv = 1.0f / sum;
#pragma unroll
        for (int e = 0; e < EM; e++) p[e] *= inv;
        int e0 = 0;
#pragma unroll
        for (int e = 1; e < EM; e++) if (p[e] > p[e0]) e0 = e;
        int e1 = -1;
#pragma unroll
        for (int e = 0; e < EM; e++) {
            if (e == e0) continue;
            if (e1 < 0 || p[e] > p[e1]) e1 = e;
        }
        int s0 = atomicAdd(&g_count[e0], 1);
        g_bucket[e0 * T_TOK + s0] = t; g_gate[e0 * T_TOK + s0] = p[e0];
        g_slot[t * KM + 0] = e0 * T_TOK + s0;
        int s1 = atomicAdd(&g_count[e1], 1);
        g_bucket[e1 * T_TOK + s1] = t; g_gate[e1 * T_TOK + s1] = p[e1];
        g_slot[t * KM + 1] = e1 * T_TOK + s1;
    }
}

// =============== GEMM1: H = silu(x Wg) * (x Wu), wmma, BK=64 ==================
// Block 128M x 64F dual. 8 warps: wm=warp&3 (4x32M), wn=warp>>2 (2x32F).
// 3-stage cp.async pipeline, distance 2. 32 k-iters.
// Grid y in [0, FM/64) -> GEMM work; y in [FM/64, FM/64+CVT_Y) -> Wd fp32->fp16
// conversion (overlapped with the GEMM wave; gemm1 never reads Wd).
#define G1_AP 72
#define G1_BPn 72
#define G1_AB (128 * G1_AP * 2)            // 18432
#define G1_BB (64 * G1_BPn * 2)            // 9216
#define G1_STAGE (G1_AB + 2 * G1_BB)       // 36864
#define G1_NS 3
#define G1_PIPE  (G1_NS * G1_STAGE)        // 110592
#define G1_SMEM  (G1_PIPE + 512)
#define G1_FY    (FM / 64)                 // 128 gemm y-tiles
#define CVT_Y    64                        // extra y-slots for Wd convert
#define CVT_BLOCKS (16 * CVT_Y * EM)       // 4096
#define CVT_PER_BLK ((EM * DM * FM / 4) / CVT_BLOCKS)   // 4096 float4 per block

__global__ __launch_bounds__(256, 2)
void gemm1_kernel(const float* __restrict__ Wd) {
    extern __shared__ char sm[];
    const int e   = blockIdx.z;

    if (blockIdx.y >= G1_FY) {
        // ---- fused Wd fp32->fp16 convert (grid-strided) ----
        const int q = blockIdx.x + 16 * ((blockIdx.y - G1_FY) + CVT_Y * blockIdx.z);
        const size_t base = (size_t)q * CVT_PER_BLK;
        const float4* src = (const float4*)Wd;
        uint2* dst = (uint2*)g_Wdh;
#pragma unroll 4
        for (int j = 0; j < CVT_PER_BLK; j += 256) {
            const size_t i = base + j + threadIdx.x;
            float4 v = src[i];
            __half2 h0 = __floats2half2_rn(v.x, v.y);
            __half2 h1 = __floats2half2_rn(v.z, v.w);
            uint2 o;
            o.x = *(uint32_t*)&h0; o.y = *(uint32_t*)&h1;
            dst[i] = o;
        }
        return;
    }

    const int cnt = g_count[e];
    const int m0  = blockIdx.x * 128;
    if (m0 >= cnt) return;
    const int f0  = blockIdx.y * 64;

    const int tid = threadIdx.x, warp = tid >> 5;
    const int wm = warp & 3, wn = warp >> 2;
    const uint32_t sb = smem_u32(sm);
    int* rows = (int*)(sm + G1_PIPE);

    if (tid < 128) {
        const int m = m0 + tid;
        rows[tid] = (m < cnt) ? g_bucket[e * T_TOK + m] : -1;
    }
    __syncthreads();

    const __half* Wge = g_Wgh + (size_t)e * DM * FM + f0;   // [d][f] natural
    const __half* Wue = g_Wuh + (size_t)e * DM * FM + f0;

    auto load_tile = [&](int s, int kt) {
        const int k0 = kt * 64;
        const uint32_t ab = sb + s * G1_STAGE;
#pragma unroll
        for (int p = 0; p < 4; p++) {                  // A: 128 rows x 8 chunks = 1024
            const int idx = tid + p * 256;
            const int rr = idx >> 3, c = idx & 7;
            const int tok = rows[rr];
            const __half* src = (tok >= 0) ? (g_xh + (size_t)tok * DM + k0 + c * 8) : g_xh;
            cpa16(ab + rr * (G1_AP * 2) + c * 16, src, (tok >= 0) ? 16u : 0u);
        }
#pragma unroll
        for (int p = 0; p < 2; p++) {                  // Bg: 64 k-rows x 8 chunks = 512
            const int idx = tid + p * 256;
            const int kr = idx >> 3, c = idx & 7;
            cpa16(ab + G1_AB + kr * (G1_BPn * 2) + c * 16,
                  Wge + (size_t)(k0 + kr) * FM + c * 8, 16);
        }
#pragma unroll
        for (int p = 0; p < 2; p++) {                  // Bu
            const int idx = tid + p * 256;
            const int kr = idx >> 3, c = idx & 7;
            cpa16(ab + G1_AB + G1_BB + kr * (G1_BPn * 2) + c * 16,
                  Wue + (size_t)(k0 + kr) * FM + c * 8, 16);
        }
    };

    wmma::fragment<wmma::accumulator, 16, 16, 16, float> cG[2][2], cU[2][2];
#pragma unroll
    for (int mi = 0; mi < 2; mi++)
#pragma unroll
        for (int ni = 0; ni < 2; ni++) {
            wmma::fill_fragment(cG[mi][ni], 0.0f);
            wmma::fill_fragment(cU[mi][ni], 0.0f);
        }

    const int KT = DM / 64;   // 32
    load_tile(0, 0); CP_COMMIT();
    load_tile(1, 1); CP_COMMIT();

    for (int kt = 0; kt < KT; kt++) {
        CP_WAIT1();
        __syncthreads();
        if (kt + 2 < KT) load_tile((kt + 2) % 3, kt + 2);

        const __half* As = (const __half*)(sm + (kt % 3) * G1_STAGE);
        const __half* Bg = As + 128 * G1_AP;
        const __half* Bu = Bg + 64 * G1_BPn;

#pragma unroll
        for (int ks = 0; ks < 4; ks++) {
            wmma::fragment<wmma::matrix_b, 16, 16, 16, __half, wmma::row_major> fbG[2], fbU[2];
#pragma unroll
            for (int ni = 0; ni < 2; ni++) {
                wmma::load_matrix_sync(fbG[ni], Bg + ks * 16 * G1_BPn + wn * 32 + ni * 16, G1_BPn);
                wmma::load_matrix_sync(fbU[ni], Bu + ks * 16 * G1_BPn + wn * 32 + ni * 16, G1_BPn);
            }
#pragma unroll
            for (int mi = 0; mi < 2; mi++) {
                wmma::fragment<wmma::matrix_a, 16, 16, 16, __half, wmma::row_major> fa;
                wmma::load_matrix_sync(fa, As + (wm * 32 + mi * 16) * G1_AP + ks * 16, G1_AP);
#pragma unroll
                for (int ni = 0; ni < 2; ni++) {
                    wmma::mma_sync(cG[mi][ni], fa, fbG[ni], cG[mi][ni]);
                    wmma::mma_sync(cU[mi][ni], fa, fbU[ni], cU[mi][ni]);
                }
            }
        }
        CP_COMMIT();
    }

    // epilogue: stage accs to smem (reuse pipeline memory), fuse silu, write half H
    __syncthreads();
    float* sg = (float*)sm;                 // 128x64 floats = 32KB
    float* su = sg + 128 * 64;              // next 32KB
#pragma unroll
    for (int mi = 0; mi < 2; mi++)
#pragma unroll
        for (int ni = 0; ni < 2; ni++) {
            const int r = wm * 32 + mi * 16, c = wn * 32 + ni * 16;
            wmma::store_matrix_sync(sg + r * 64 + c, cG[mi][ni], 64, wmma::mem_row_major);
            wmma::store_matrix_sync(su + r * 64 + c, cU[mi][ni], 64, wmma::mem_row_major);
        }
    __syncthreads();
    for (int i = tid; i < 128 * 64; i += 256) {
        const int r = i >> 6, c = i & 63;
        const float g = sg[i], u = su[i];
        g_Hh[((size_t)(e * T_TOK) + m0 + r) * FM + f0 + c] = __float2half_rn(silu_f(g) * u);
    }
}

// =============== GEMM2: Y = H Wd, wmma, BK=64 =================================
// Block 128M x 128N. 8 warps: wm=warp&1 (2x64M), wn=warp>>1 (4x32N).
// 3-stage cp.async pipeline, distance 2. 128 k-iters.
#define G2_AP 72
#define G2_BPn 136
#define G2_AB (128 * G2_AP * 2)             // 18432
#define G2_BB (64 * G2_BPn * 2)             // 17408
#define G2_STAGE (G2_AB + G2_BB)            // 35840
#define G2_NS 3
#define G2_SMEM  (G2_NS * G2_STAGE)         // 107520

__global__ __launch_bounds__(256, 2)
void gemm2_kernel() {
    extern __shared__ char sm[];
    const int e   = blockIdx.z;
    const int cnt = g_count[e];
    const int m0  = blockIdx.x * 128;
    if (m0 >= cnt) return;
    const int d0  = blockIdx.y * 128;

    const int tid = threadIdx.x, warp = tid >> 5;
    const int wm = warp & 1, wn = warp >> 1;
    const uint32_t sb = smem_u32(sm);

    const __half* Hb  = g_Hh + (size_t)(e * T_TOK + m0) * FM;
    const __half* Wde = g_Wdh + (size_t)e * FM * DM + d0;    // [f][d] natural

    auto load_tile = [&](int s, int kt) {
        const int k0 = kt * 64;
        const uint32_t ab = sb + s * G2_STAGE;
#pragma unroll
        for (int p = 0; p < 4; p++) {                  // A: 128 rows x 8 chunks = 1024
            const int idx = tid + p * 256;
            const int rr = idx >> 3, c = idx & 7;
            cpa16(ab + rr * (G2_AP * 2) + c * 16, Hb + (size_t)rr * FM + k0 + c * 8, 16);
        }
#pragma unroll
        for (int p = 0; p < 4; p++) {                  // B: 64 k-rows x 16 chunks = 1024
            const int idx = tid + p * 256;
            const int kr = idx >> 4, c = idx & 15;
            cpa16(ab + G2_AB + kr * (G2_BPn * 2) + c * 16,
                  Wde + (size_t)(k0 + kr) * DM + c * 8, 16);
        }
    };

    wmma::fragment<wmma::accumulator, 16, 16, 16, float> cY[4][2];
#pragma unroll
    for (int mi = 0; mi < 4; mi++)
#pragma unroll
        for (int ni = 0; ni < 2; ni++)
            wmma::fill_fragment(cY[mi][ni], 0.0f);

    const int KT = FM / 64;   // 128
    load_tile(0, 0); CP_COMMIT();
    load_tile(1, 1); CP_COMMIT();

    for (int kt = 0; kt < KT; kt++) {
        CP_WAIT1();
        __syncthreads();
        if (kt + 2 < KT) load_tile((kt + 2) % 3, kt + 2);

        const __half* As = (const __half*)(sm + (kt % 3) * G2_STAGE);
        const __half* Bs = As + 128 * G2_AP;

#pragma unroll
        for (int ks = 0; ks < 4; ks++) {
            wmma::fragment<wmma::matrix_b, 16, 16, 16, __half, wmma::row_major> fb[2];
#pragma unroll
            for (int ni = 0; ni < 2; ni++)
                wmma::load_matrix_sync(fb[ni], Bs + ks * 16 * G2_BPn + wn * 32 + ni * 16, G2_BPn);
#pragma unroll
            for (int mi = 0; mi < 4; mi++) {
                wmma::fragment<wmma::matrix_a, 16, 16, 16, __half, wmma::row_major> fa;
                wmma::load_matrix_sync(fa, As + (wm * 64 + mi * 16) * G2_AP + ks * 16, G2_AP);
#pragma unroll
                for (int ni = 0; ni < 2; ni++)
                    wmma::mma_sync(cY[mi][ni], fa, fb[ni], cY[mi][ni]);
            }
        }
        CP_COMMIT();
    }

    // direct gmem store (fp32, ldm = DM)
#pragma unroll
    for (int mi = 0; mi < 4; mi++)
#pragma unroll
        for (int ni = 0; ni < 2; ni++) {
            float* dst = g_Y + ((size_t)(e * T_TOK) + m0 + wm * 64 + mi * 16) * DM
                             + d0 + wn * 32 + ni * 16;
            wmma::store_matrix_sync(dst, cY[mi][ni], DM, wmma::mem_row_major);
        }
}

__global__ void combine_kernel(float* __restrict__ out) {
    const int i = blockIdx.x * blockDim.x + threadIdx.x;
    const int t = i / (DM / 4), c = i % (DM / 4);
    const int s0 = g_slot[t * KM + 0], s1 = g_slot[t * KM + 1];
    const float w0 = g_gate[s0], w1 = g_gate[s1];
    const float4 y0 = *((const float4*)g_Y + (size_t)s0 * (DM / 4) + c);
    const float4 y1 = *((const float4*)g_Y + (size_t)s1 * (DM / 4) + c);
    float4 o;
    o.x = w0 * y0.x + w1 * y1.x; o.y = w0 * y0.y + w1 * y1.y;
    o.z = w0 * y0.z + w1 * y1.z; o.w = w0 * y0.w + w1 * y1.w;
    *((float4*)out + i) = o;
}

// ---------------- launch ------------------------------------------------------
extern "C" void kernel_launch(void* const* d_in, const int* in_sizes, int n_in,
                              void* d_out, int out_size) {
    const float* x  = (const float*)d_in[0];
    const float* Wr = (const float*)d_in[1];
    const float* Wg = (const float*)d_in[2];
    const float* Wu = (const float*)d_in[3];
    const float* Wd = (const float*)d_in[4];
    float* out = (float*)d_out;

    cudaFuncSetAttribute(gemm1_kernel, cudaFuncAttributeMaxDynamicSharedMemorySize, G1_SMEM);
    cudaFuncSetAttribute(gemm2_kernel, cudaFuncAttributeMaxDynamicSharedMemorySize, G2_SMEM);

    const int WQ = (EM * DM * FM) / 4 / 256;     // float4 blocks per weight
    init_counts_kernel<<<1, 32>>>();
    cvt_x_kernel<<<T_TOK * DM / 4 / 256, 256>>>(x);
    cvt_w_kernel<<<dim3(WQ, 2), 256>>>(Wg, Wu);          // Wg, Wu only
    router_kernel<<<T_TOK, 128>>>(x, Wr);
    gemm1_kernel<<<dim3(T_TOK / 128, G1_FY + CVT_Y, EM), 256, G1_SMEM>>>(Wd);
    gemm2_kernel<<<dim3(T_TOK / 128, DM / 128, EM), 256, G2_SMEM>>>();
    combine_kernel<<<(T_TOK * DM / 4) / 256, 256>>>(out);
}